// round 10
// baseline (speedup 1.0000x reference)
#include <cuda_runtime.h>
#include <cuda_bf16.h>
#include <cstdint>

#define NN 100000
#define ROWSP 100096           // NN padded to multiple of 128
#define NE 3200000
#define IND 512
#define HID 256
#define NC  64

// ---------------- scratch (static device globals; no runtime allocation) ----
__device__ float g_tb[3][(size_t)NN * NC];                     // rotating T_k buffers
__device__ int   g_rp[NN + 1];                                 // CSR row_ptr
__device__ __align__(128) __nv_bfloat16 g_ahi[(size_t)8 * ROWSP * 64];
__device__ __align__(128) __nv_bfloat16 g_alo[(size_t)8 * ROWSP * 64];
__device__ __align__(128) __nv_bfloat16 g_hhi[(size_t)4 * ROWSP * 64];
__device__ __align__(128) __nv_bfloat16 g_hlo[(size_t)4 * ROWSP * 64];
__device__ __align__(128) __nv_bfloat16 g_w1hi[8 * 256 * 64], g_w1lo[8 * 256 * 64];
__device__ __align__(128) __nv_bfloat16 g_w2hi[4 * 64 * 64],  g_w2lo[4 * 64 * 64];

// ---------------- inline PTX helpers (base ISA only) ------------------------
__device__ __forceinline__ uint32_t smem_u32(const void* p) {
    uint32_t a;
    asm("{ .reg .u64 t; cvta.to.shared.u64 t, %1; cvt.u32.u64 %0, t; }" : "=r"(a) : "l"(p));
    return a;
}
#define MBARRIER_INIT(addr, cnt) \
    asm volatile("mbarrier.init.shared.b64 [%0], %1;" :: "r"(addr), "r"((uint32_t)(cnt)) : "memory")
#define MBARRIER_INVAL(addr) \
    asm volatile("mbarrier.inval.shared.b64 [%0];" :: "r"(addr) : "memory")
#define MBARRIER_EXPECT_TX(addr, bytes) \
    asm volatile("mbarrier.arrive.expect_tx.shared.b64 _, [%0], %1;" :: "r"(addr), "r"((uint32_t)(bytes)) : "memory")
__device__ __forceinline__ void mbar_wait(uint32_t mbar, uint32_t parity) {
    asm volatile(
        "{\n\t.reg .pred P1;\n\t"
        "WAIT_LOOP_%=:\n\t"
        "mbarrier.try_wait.parity.acquire.cta.shared::cta.b64 P1, [%0], %1, 0x989680;\n\t"
        "@P1 bra.uni WAIT_DONE_%=;\n\t"
        "bra.uni WAIT_LOOP_%=;\n\t"
        "WAIT_DONE_%=:\n\t}"
        :: "r"(mbar), "r"(parity) : "memory");
}
#define BULK_G2S(dst, src, bytes, mbar) \
    asm volatile("cp.async.bulk.shared::cta.global.mbarrier::complete_tx::bytes [%0], [%1], %2, [%3];" \
        :: "r"((uint32_t)(dst)), "l"(src), "r"((uint32_t)(bytes)), "r"((uint32_t)(mbar)) : "memory")

__device__ __forceinline__ void ldsm4(uint32_t* r, uint32_t addr) {
    asm volatile("ldmatrix.sync.aligned.m8n8.x4.shared.b16 {%0,%1,%2,%3}, [%4];"
        : "=r"(r[0]), "=r"(r[1]), "=r"(r[2]), "=r"(r[3]) : "r"(addr));
}
__device__ __forceinline__ void mma_bf16(float* d, const uint32_t* a, const uint32_t* b) {
    asm volatile("mma.sync.aligned.m16n8k16.row.col.f32.bf16.bf16.f32 "
        "{%0,%1,%2,%3}, {%4,%5,%6,%7}, {%8,%9}, {%0,%1,%2,%3};"
        : "+f"(d[0]), "+f"(d[1]), "+f"(d[2]), "+f"(d[3])
        : "r"(a[0]), "r"(a[1]), "r"(a[2]), "r"(a[3]), "r"(b[0]), "r"(b[1]));
}

// ---------------- prep kernels ----------------------------------------------
template <int KSHIFT>
__global__ void prep_a(const float* __restrict__ src,
                       __nv_bfloat16* __restrict__ dhi, __nv_bfloat16* __restrict__ dlo) {
    constexpr int K = 1 << KSHIFT;
    constexpr int G = K / 8;
    long long idx = (long long)blockIdx.x * blockDim.x + threadIdx.x;
    if (idx >= (long long)NN * G) return;
    int r = (int)(idx / G);
    int g = (int)(idx % G);
    int k = g * 8;
    int c = k >> 6, kk = k & 63;

    const float4* s4 = (const float4*)(src + (size_t)r * K + k);
    float4 v0 = s4[0], v1 = s4[1];
    float f[8] = {v0.x, v0.y, v0.z, v0.w, v1.x, v1.y, v1.z, v1.w};
    __nv_bfloat162 hi[4], lo[4];
#pragma unroll
    for (int i = 0; i < 4; ++i) {
        __nv_bfloat16 h0 = __float2bfloat16(f[2 * i]);
        __nv_bfloat16 h1 = __float2bfloat16(f[2 * i + 1]);
        hi[i] = __nv_bfloat162(h0, h1);
        lo[i] = __nv_bfloat162(__float2bfloat16(f[2 * i] - __bfloat162float(h0)),
                               __float2bfloat16(f[2 * i + 1] - __bfloat162float(h1)));
    }
    uint32_t off = (uint32_t)r * 128 + (((uint32_t)kk * 2) ^ (((uint32_t)r & 7) << 4));
    size_t pbase = (size_t)c * ROWSP * 128;
    *(uint4*)((char*)dhi + pbase + off) = *(uint4*)hi;
    *(uint4*)((char*)dlo + pbase + off) = *(uint4*)lo;
}

template <int NSHIFT>
__global__ void prep_w(const float* __restrict__ src, int K,
                       __nv_bfloat16* __restrict__ dhi, __nv_bfloat16* __restrict__ dlo) {
    constexpr int N = 1 << NSHIFT;
    int idx = blockIdx.x * blockDim.x + threadIdx.x;
    if (idx >= K * N) return;
    int k = idx >> NSHIFT;
    int n = idx & (N - 1);
    int c = k >> 6, kk = k & 63;
    float v = src[idx];
    __nv_bfloat16 hi = __float2bfloat16(v);
    __nv_bfloat16 lo = __float2bfloat16(v - __bfloat162float(hi));
    int poff = (kk << 1) ^ ((n & 7) << 4);
    size_t dst = ((size_t)c * N + n) * 64 + (poff >> 1);
    dhi[dst] = hi;
    dlo[dst] = lo;
}

// ---------------- split-bf16 mma.sync GEMM, 256 threads, 2-stage ------------
// D[128, BN] = A[128, K] @ B[BN, K]^T; 3 split products per 64-chunk.
// (R5-measured mainloop: 8 warps, double buffer, m-fast grid.)
template <int BN, int NCHUNK, int WM, int WN, bool SPLIT_OUT>
__global__ void __launch_bounds__(256)
tc_gemm(const __nv_bfloat16* __restrict__ Ahi, const __nv_bfloat16* __restrict__ Alo,
        const __nv_bfloat16* __restrict__ Bhi, const __nv_bfloat16* __restrict__ Blo,
        const float* __restrict__ bias, float* __restrict__ C,
        __nv_bfloat16* __restrict__ Ohi, __nv_bfloat16* __restrict__ Olo, int NB) {
    constexpr int WR = 128 / WM;
    constexpr int WC = BN / WN;
    constexpr int MT = WR / 16;
    constexpr int NT = WC / 8;
    constexpr uint32_t BNB = BN * 128;
    constexpr uint32_t BUFB = 32768 + 2 * BNB;

    extern __shared__ char smem[];
    const uint32_t sb = smem_u32(smem);
    const int tid = threadIdx.x;
    const int lane = tid & 31;
    const int wid = tid >> 5;
    const int wm = wid / WN, wn = wid % WN;
    const int bm = blockIdx.x * 128;           // m fast (R5 layout)
    const int n0 = blockIdx.y * BN;

    const uint32_t mb0 = sb + 8, mb1 = sb + 24;
    if (tid == 0) { MBARRIER_INIT(mb0, 1); MBARRIER_INIT(mb1, 1); }
    __syncthreads();

    auto issue = [&](int c) {
        int buf = c & 1;
        uint32_t mb = buf ? mb1 : mb0;
        uint32_t base = sb + 1024 + (uint32_t)buf * BUFB;
        MBARRIER_EXPECT_TX(mb, BUFB);
        const char* ah = (const char*)Ahi + ((size_t)c * ROWSP + bm) * 128;
        const char* al = (const char*)Alo + ((size_t)c * ROWSP + bm) * 128;
        const char* bh = (const char*)Bhi + ((size_t)c * NB + n0) * 128;
        const char* bl = (const char*)Blo + ((size_t)c * NB + n0) * 128;
        BULK_G2S(base,               ah, 16384, mb);
        BULK_G2S(base + 16384,       al, 16384, mb);
        BULK_G2S(base + 32768,       bh, BNB,   mb);
        BULK_G2S(base + 32768 + BNB, bl, BNB,   mb);
    };
    if (tid == 0) {
#pragma unroll
        for (int c = 0; c < 2 && c < NCHUNK; ++c) issue(c);
    }

    const int arow = lane & 15;
    const int akb = (lane >> 4) << 3;
    const uint32_t aRowOff = (uint32_t)(wm * WR + arow) * 128;
    const uint32_t aSw = (uint32_t)(arow & 7) << 4;
    const int brow = (lane & 7) + ((lane >> 4) << 3);
    const int bkb = ((lane >> 3) & 1) << 3;
    const uint32_t bRowOff = (uint32_t)(wn * WC + brow) * 128;
    const uint32_t bSw = (uint32_t)(brow & 7) << 4;

    float acc[MT][NT][4];
#pragma unroll
    for (int i = 0; i < MT; ++i)
#pragma unroll
        for (int j = 0; j < NT; ++j)
#pragma unroll
            for (int q = 0; q < 4; ++q) acc[i][j][q] = 0.f;

    for (int c = 0; c < NCHUNK; ++c) {
        const int buf = c & 1;
        mbar_wait(buf ? mb1 : mb0, (uint32_t)(c >> 1) & 1);

        const uint32_t base = sb + 1024 + (uint32_t)buf * BUFB;
        const uint32_t aHiS = base, aLoS = base + 16384;
        const uint32_t bHiS = base + 32768, bLoS = base + 32768 + BNB;

#pragma unroll
        for (int ks = 0; ks < 4; ++ks) {
            uint32_t ah[MT][4], al[MT][4], bh[NT][2], bl[NT][2];
            const uint32_t akByte = ((uint32_t)((ks * 16 + akb) * 2)) ^ aSw;
#pragma unroll
            for (int mt = 0; mt < MT; ++mt) {
                uint32_t o = aRowOff + (uint32_t)mt * 2048 + akByte;
                ldsm4(ah[mt], aHiS + o);
                ldsm4(al[mt], aLoS + o);
            }
            const uint32_t bkByte = ((uint32_t)((ks * 16 + bkb) * 2)) ^ bSw;
#pragma unroll
            for (int p = 0; p < NT / 2; ++p) {
                uint32_t o = bRowOff + (uint32_t)p * 2048 + bkByte;
                uint32_t t[4];
                ldsm4(t, bHiS + o);
                bh[2 * p][0] = t[0]; bh[2 * p][1] = t[1];
                bh[2 * p + 1][0] = t[2]; bh[2 * p + 1][1] = t[3];
                ldsm4(t, bLoS + o);
                bl[2 * p][0] = t[0]; bl[2 * p][1] = t[1];
                bl[2 * p + 1][0] = t[2]; bl[2 * p + 1][1] = t[3];
            }
#pragma unroll
            for (int mt = 0; mt < MT; ++mt)
#pragma unroll
                for (int nt = 0; nt < NT; ++nt)
                    mma_bf16(acc[mt][nt], ah[mt], bh[nt]);
#pragma unroll
            for (int mt = 0; mt < MT; ++mt)
#pragma unroll
                for (int nt = 0; nt < NT; ++nt)
                    mma_bf16(acc[mt][nt], ah[mt], bl[nt]);
#pragma unroll
            for (int mt = 0; mt < MT; ++mt)
#pragma unroll
                for (int nt = 0; nt < NT; ++nt)
                    mma_bf16(acc[mt][nt], al[mt], bh[nt]);
        }
        __syncthreads();
        if (tid == 0 && c + 2 < NCHUNK) issue(c + 2);
    }

    // epilogue
    const int r0 = bm + wm * WR + (lane >> 2);
#pragma unroll
    for (int mt = 0; mt < MT; ++mt) {
#pragma unroll
        for (int nt = 0; nt < NT; ++nt) {
            int row = r0 + mt * 16;
            int col = n0 + wn * WC + nt * 8 + (lane & 3) * 2;
            float bv0 = __ldg(bias + col), bv1 = __ldg(bias + col + 1);
            if (SPLIT_OUT) {
                int pl = col >> 6, kk = col & 63;
                size_t pbase = (size_t)pl * ROWSP * 128;
                uint32_t xoff = ((uint32_t)kk * 2);
#pragma unroll
                for (int half = 0; half < 2; ++half) {
                    int r = row + half * 8;
                    if (r >= NN) continue;
                    float v0 = fmaxf(acc[mt][nt][2 * half + 0] + bv0, 0.f);
                    float v1 = fmaxf(acc[mt][nt][2 * half + 1] + bv1, 0.f);
                    __nv_bfloat16 h0 = __float2bfloat16(v0);
                    __nv_bfloat16 h1 = __float2bfloat16(v1);
                    __nv_bfloat162 hv(h0, h1);
                    __nv_bfloat162 lv(__float2bfloat16(v0 - __bfloat162float(h0)),
                                      __float2bfloat16(v1 - __bfloat162float(h1)));
                    uint32_t off = (uint32_t)r * 128 + (xoff ^ (((uint32_t)r & 7) << 4));
                    *(__nv_bfloat162*)((char*)Ohi + pbase + off) = hv;
                    *(__nv_bfloat162*)((char*)Olo + pbase + off) = lv;
                }
            } else {
#pragma unroll
                for (int half = 0; half < 2; ++half) {
                    int r = row + half * 8;
                    if (r >= NN) continue;
                    float2 v;
                    v.x = acc[mt][nt][2 * half + 0] + bv0;
                    v.y = acc[mt][nt][2 * half + 1] + bv1;
                    *(float2*)&C[(size_t)r * NB + col] = v;
                }
            }
        }
    }
    __syncthreads();
    if (tid == 0) { MBARRIER_INVAL(mb0); MBARRIER_INVAL(mb1); }
}

// ---------------- row_ptr build ---------------------------------------------
__global__ void build_row_ptr(const int* __restrict__ erow) {
    int r = blockIdx.x * blockDim.x + threadIdx.x;
    if (r > NN) return;
    int lo = 0, hi = NE;
    while (lo < hi) {
        int mid = (lo + hi) >> 1;
        if (erow[mid] < r) lo = mid + 1; else hi = mid;
    }
    g_rp[r] = lo;
}

// ---------------- fused CSR SpMM + Chebyshev recurrence ---------------------
// 16 threads/row, unroll-4 with two independent accumulator chains (no reg cap).
__global__ void spmm_cheb(const int* __restrict__ ecol, const float* __restrict__ evals,
                          const float* __restrict__ gamma, float* __restrict__ z,
                          int cur, int prev, int nxt, int k, int first, int last) {
    int t = blockIdx.x * blockDim.x + threadIdx.x;
    int row = t >> 4;
    int ch = t & 15;
    if (row >= NN) return;

    const float4* vcur = (const float4*)g_tb[cur];
    int s = g_rp[row];
    int e = g_rp[row + 1];

    float4 acc0 = make_float4(0.f, 0.f, 0.f, 0.f);
    float4 acc1 = make_float4(0.f, 0.f, 0.f, 0.f);
    int i = s;
    int nb = (e - s) >> 2;
    for (int b = 0; b < nb; ++b, i += 4) {
        int c0 = __ldg(ecol + i + 0), c1 = __ldg(ecol + i + 1);
        int c2 = __ldg(ecol + i + 2), c3 = __ldg(ecol + i + 3);
        float w0 = __ldg(evals + i + 0), w1 = __ldg(evals + i + 1);
        float w2 = __ldg(evals + i + 2), w3 = __ldg(evals + i + 3);
        float4 v0 = __ldg(vcur + (size_t)c0 * 16 + ch);
        float4 v1 = __ldg(vcur + (size_t)c1 * 16 + ch);
        float4 v2 = __ldg(vcur + (size_t)c2 * 16 + ch);
        float4 v3 = __ldg(vcur + (size_t)c3 * 16 + ch);
        acc0.x = fmaf(w0, v0.x, acc0.x); acc0.y = fmaf(w0, v0.y, acc0.y);
        acc0.z = fmaf(w0, v0.z, acc0.z); acc0.w = fmaf(w0, v0.w, acc0.w);
        acc1.x = fmaf(w1, v1.x, acc1.x); acc1.y = fmaf(w1, v1.y, acc1.y);
        acc1.z = fmaf(w1, v1.z, acc1.z); acc1.w = fmaf(w1, v1.w, acc1.w);
        acc0.x = fmaf(w2, v2.x, acc0.x); acc0.y = fmaf(w2, v2.y, acc0.y);
        acc0.z = fmaf(w2, v2.z, acc0.z); acc0.w = fmaf(w2, v2.w, acc0.w);
        acc1.x = fmaf(w3, v3.x, acc1.x); acc1.y = fmaf(w3, v3.y, acc1.y);
        acc1.z = fmaf(w3, v3.z, acc1.z); acc1.w = fmaf(w3, v3.w, acc1.w);
    }
    for (; i < e; ++i) {
        int col = __ldg(ecol + i);
        float w = __ldg(evals + i);
        float4 v = __ldg(vcur + (size_t)col * 16 + ch);
        acc0.x = fmaf(w, v.x, acc0.x);
        acc0.y = fmaf(w, v.y, acc0.y);
        acc0.z = fmaf(w, v.z, acc0.z);
        acc0.w = fmaf(w, v.w, acc0.w);
    }
    float4 acc;
    acc.x = acc0.x + acc1.x;
    acc.y = acc0.y + acc1.y;
    acc.z = acc0.z + acc1.z;
    acc.w = acc0.w + acc1.w;

    size_t o = (size_t)row * 16 + ch;
    float4* vnext = (float4*)g_tb[nxt];
    float4* z4 = (float4*)z;

    if (first) {
        float g0 = gamma[0], g1 = gamma[1];
        float4 h = vcur[o];
        vnext[o] = acc;
        float4 zz;
        zz.x = g0 * h.x + g1 * acc.x;
        zz.y = g0 * h.y + g1 * acc.y;
        zz.z = g0 * h.z + g1 * acc.z;
        zz.w = g0 * h.w + g1 * acc.w;
        z4[o] = zz;
    } else {
        const float4* vprev = (const float4*)g_tb[prev];
        float4 p = vprev[o];
        float4 tn;
        tn.x = 2.f * acc.x - p.x;
        tn.y = 2.f * acc.y - p.y;
        tn.z = 2.f * acc.z - p.z;
        tn.w = 2.f * acc.w - p.w;
        if (!last) vnext[o] = tn;
        float g = gamma[k];
        float4 zz = z4[o];
        zz.x = fmaf(g, tn.x, zz.x);
        zz.y = fmaf(g, tn.y, zz.y);
        zz.z = fmaf(g, tn.z, zz.z);
        zz.w = fmaf(g, tn.w, zz.w);
        z4[o] = zz;
    }
}

// ---------------- launch ----------------------------------------------------
extern "C" void kernel_launch(void* const* d_in, const int* in_sizes, int n_in,
                              void* d_out, int out_size) {
    const float* x     = (const float*)d_in[0];
    const int*   erow  = (const int*)d_in[1];
    const int*   ecol  = (const int*)d_in[2];
    const float* evals = (const float*)d_in[3];
    const float* W1    = (const float*)d_in[4];
    const float* b1    = (const float*)d_in[5];
    const float* W2    = (const float*)d_in[6];
    const float* b2    = (const float*)d_in[7];
    const float* gamma = (const float*)d_in[8];
    float* z = (float*)d_out;

    float *tb0;
    __nv_bfloat16 *ahi, *alo, *hhi, *hlo, *w1hi, *w1lo, *w2hi, *w2lo;
    cudaGetSymbolAddress((void**)&tb0, g_tb);
    cudaGetSymbolAddress((void**)&ahi, g_ahi);
    cudaGetSymbolAddress((void**)&alo, g_alo);
    cudaGetSymbolAddress((void**)&hhi, g_hhi);
    cudaGetSymbolAddress((void**)&hlo, g_hlo);
    cudaGetSymbolAddress((void**)&w1hi, g_w1hi);
    cudaGetSymbolAddress((void**)&w1lo, g_w1lo);
    cudaGetSymbolAddress((void**)&w2hi, g_w2hi);
    cudaGetSymbolAddress((void**)&w2lo, g_w2lo);

    // dynamic smem: 1024 + 2 * (32768 + 2*BN*128)
    constexpr int SMEM1 = 1024 + 2 * (32768 + 2 * 128 * 128);  // 132096
    constexpr int SMEM2 = 1024 + 2 * (32768 + 2 * 64 * 128);   // 99328
    cudaFuncSetAttribute(tc_gemm<128, 8, 2, 4, true>,
                         cudaFuncAttributeMaxDynamicSharedMemorySize, SMEM1);
    cudaFuncSetAttribute(tc_gemm<64, 4, 4, 2, false>,
                         cudaFuncAttributeMaxDynamicSharedMemorySize, SMEM2);

    const int MTILES = (NN + 127) / 128;  // 782

    prep_w<8><<<(IND * HID + 255) / 256, 256>>>(W1, IND, w1hi, w1lo);
    prep_w<6><<<(HID * NC + 255) / 256, 256>>>(W2, HID, w2hi, w2lo);

    {
        long long tot = (long long)NN * (IND / 8);
        prep_a<9><<<(unsigned)((tot + 255) / 256), 256>>>(x, ahi, alo);
    }
    // GEMM1: relu(x@W1 + b1) -> split bf16 planes (g_hhi/g_hlo)
    {
        dim3 grid(MTILES, 2);   // m fast (R5-measured best)
        tc_gemm<128, 8, 2, 4, true><<<grid, 256, SMEM1>>>(
            ahi, alo, w1hi, w1lo, b1, nullptr, hhi, hlo, HID);
    }
    // GEMM2: h@W2 + b2 -> g_tb[0] fp32
    {
        dim3 grid(MTILES, 1);
        tc_gemm<64, 4, 4, 2, false><<<grid, 256, SMEM2>>>(
            hhi, hlo, w2hi, w2lo, b2, tb0, nullptr, nullptr, NC);
    }

    build_row_ptr<<<(NN + 256) / 256, 256>>>(erow);

    const int SPMM_BLOCKS = (NN * 16 + 255) / 256;
    spmm_cheb<<<SPMM_BLOCKS, 256>>>(ecol, evals, gamma, z, 0, 0, 1, 1, 1, 0);
    int p = 0, c = 1;
    for (int k = 2; k <= 8; ++k) {
        int n = 3 - p - c;
        spmm_cheb<<<SPMM_BLOCKS, 256>>>(ecol, evals, gamma, z, c, p, n, k, 0, k == 8);
        p = c; c = n;
    }
}

// round 11
// speedup vs baseline: 1.5116x; 1.5116x over previous
#include <cuda_runtime.h>
#include <cuda_bf16.h>
#include <cstdint>

#define NN 100000
#define ROWSP 100096           // NN padded to multiple of 128
#define NE 3200000
#define IND 512
#define HID 256
#define NC  64

// ---------------- scratch (static device globals; no runtime allocation) ----
__device__ float g_tb[3][(size_t)NN * NC];                     // rotating T_k buffers
__device__ int   g_rp[NN + 1];                                 // CSR row_ptr
__device__ __align__(128) __nv_bfloat16 g_ahi[(size_t)8 * ROWSP * 64];
__device__ __align__(128) __nv_bfloat16 g_alo[(size_t)8 * ROWSP * 64];
__device__ __align__(128) __nv_bfloat16 g_hhi[(size_t)4 * ROWSP * 64];
__device__ __align__(128) __nv_bfloat16 g_hlo[(size_t)4 * ROWSP * 64];
__device__ __align__(128) __nv_bfloat16 g_w1hi[8 * 256 * 64], g_w1lo[8 * 256 * 64];
__device__ __align__(128) __nv_bfloat16 g_w2hi[4 * 64 * 64],  g_w2lo[4 * 64 * 64];

// ---------------- inline PTX helpers (base ISA only) ------------------------
__device__ __forceinline__ uint32_t smem_u32(const void* p) {
    uint32_t a;
    asm("{ .reg .u64 t; cvta.to.shared.u64 t, %1; cvt.u32.u64 %0, t; }" : "=r"(a) : "l"(p));
    return a;
}
#define MBARRIER_INIT(addr, cnt) \
    asm volatile("mbarrier.init.shared.b64 [%0], %1;" :: "r"(addr), "r"((uint32_t)(cnt)) : "memory")
#define MBARRIER_INVAL(addr) \
    asm volatile("mbarrier.inval.shared.b64 [%0];" :: "r"(addr) : "memory")
#define MBARRIER_EXPECT_TX(addr, bytes) \
    asm volatile("mbarrier.arrive.expect_tx.shared.b64 _, [%0], %1;" :: "r"(addr), "r"((uint32_t)(bytes)) : "memory")
__device__ __forceinline__ void mbar_wait(uint32_t mbar, uint32_t parity) {
    asm volatile(
        "{\n\t.reg .pred P1;\n\t"
        "WAIT_LOOP_%=:\n\t"
        "mbarrier.try_wait.parity.acquire.cta.shared::cta.b64 P1, [%0], %1, 0x989680;\n\t"
        "@P1 bra.uni WAIT_DONE_%=;\n\t"
        "bra.uni WAIT_LOOP_%=;\n\t"
        "WAIT_DONE_%=:\n\t}"
        :: "r"(mbar), "r"(parity) : "memory");
}
#define BULK_G2S(dst, src, bytes, mbar) \
    asm volatile("cp.async.bulk.shared::cta.global.mbarrier::complete_tx::bytes [%0], [%1], %2, [%3];" \
        :: "r"((uint32_t)(dst)), "l"(src), "r"((uint32_t)(bytes)), "r"((uint32_t)(mbar)) : "memory")

__device__ __forceinline__ void ldsm4(uint32_t* r, uint32_t addr) {
    asm volatile("ldmatrix.sync.aligned.m8n8.x4.shared.b16 {%0,%1,%2,%3}, [%4];"
        : "=r"(r[0]), "=r"(r[1]), "=r"(r[2]), "=r"(r[3]) : "r"(addr));
}
__device__ __forceinline__ void mma_bf16(float* d, const uint32_t* a, const uint32_t* b) {
    asm volatile("mma.sync.aligned.m16n8k16.row.col.f32.bf16.bf16.f32 "
        "{%0,%1,%2,%3}, {%4,%5,%6,%7}, {%8,%9}, {%0,%1,%2,%3};"
        : "+f"(d[0]), "+f"(d[1]), "+f"(d[2]), "+f"(d[3])
        : "r"(a[0]), "r"(a[1]), "r"(a[2]), "r"(a[3]), "r"(b[0]), "r"(b[1]));
}

// ---------------- prep kernels ----------------------------------------------
template <int KSHIFT>
__global__ void prep_a(const float* __restrict__ src,
                       __nv_bfloat16* __restrict__ dhi, __nv_bfloat16* __restrict__ dlo) {
    constexpr int K = 1 << KSHIFT;
    constexpr int G = K / 8;
    long long idx = (long long)blockIdx.x * blockDim.x + threadIdx.x;
    if (idx >= (long long)NN * G) return;
    int r = (int)(idx / G);
    int g = (int)(idx % G);
    int k = g * 8;
    int c = k >> 6, kk = k & 63;

    const float4* s4 = (const float4*)(src + (size_t)r * K + k);
    float4 v0 = s4[0], v1 = s4[1];
    float f[8] = {v0.x, v0.y, v0.z, v0.w, v1.x, v1.y, v1.z, v1.w};
    __nv_bfloat162 hi[4], lo[4];
#pragma unroll
    for (int i = 0; i < 4; ++i) {
        __nv_bfloat16 h0 = __float2bfloat16(f[2 * i]);
        __nv_bfloat16 h1 = __float2bfloat16(f[2 * i + 1]);
        hi[i] = __nv_bfloat162(h0, h1);
        lo[i] = __nv_bfloat162(__float2bfloat16(f[2 * i] - __bfloat162float(h0)),
                               __float2bfloat16(f[2 * i + 1] - __bfloat162float(h1)));
    }
    uint32_t off = (uint32_t)r * 128 + (((uint32_t)kk * 2) ^ (((uint32_t)r & 7) << 4));
    size_t pbase = (size_t)c * ROWSP * 128;
    *(uint4*)((char*)dhi + pbase + off) = *(uint4*)hi;
    *(uint4*)((char*)dlo + pbase + off) = *(uint4*)lo;
}

template <int NSHIFT>
__global__ void prep_w(const float* __restrict__ src, int K,
                       __nv_bfloat16* __restrict__ dhi, __nv_bfloat16* __restrict__ dlo) {
    constexpr int N = 1 << NSHIFT;
    int idx = blockIdx.x * blockDim.x + threadIdx.x;
    if (idx >= K * N) return;
    int k = idx >> NSHIFT;
    int n = idx & (N - 1);
    int c = k >> 6, kk = k & 63;
    float v = src[idx];
    __nv_bfloat16 hi = __float2bfloat16(v);
    __nv_bfloat16 lo = __float2bfloat16(v - __bfloat162float(hi));
    int poff = (kk << 1) ^ ((n & 7) << 4);
    size_t dst = ((size_t)c * N + n) * 64 + (poff >> 1);
    dhi[dst] = hi;
    dlo[dst] = lo;
}

// ---------------- split-bf16 mma.sync GEMM, 256 threads, 3-stage ------------
// (exact R6-measured best configuration)
template <int BN, int NCHUNK, int WM, int WN, bool SPLIT_OUT>
__global__ void __launch_bounds__(256)
tc_gemm(const __nv_bfloat16* __restrict__ Ahi, const __nv_bfloat16* __restrict__ Alo,
        const __nv_bfloat16* __restrict__ Bhi, const __nv_bfloat16* __restrict__ Blo,
        const float* __restrict__ bias, float* __restrict__ C,
        __nv_bfloat16* __restrict__ Ohi, __nv_bfloat16* __restrict__ Olo, int NB) {
    constexpr int WR = 128 / WM;
    constexpr int WC = BN / WN;
    constexpr int MT = WR / 16;
    constexpr int NT = WC / 8;
    constexpr uint32_t BNB = BN * 128;
    constexpr uint32_t BUFB = 32768 + 2 * BNB;

    extern __shared__ char smem[];
    const uint32_t sb = smem_u32(smem);
    const int tid = threadIdx.x;
    const int lane = tid & 31;
    const int wid = tid >> 5;
    const int wm = wid / WN, wn = wid % WN;
    const int bm = blockIdx.y * 128;
    const int n0 = blockIdx.x * BN;

    if (tid == 0) {
        MBARRIER_INIT(sb + 8, 1);
        MBARRIER_INIT(sb + 24, 1);
        MBARRIER_INIT(sb + 40, 1);
    }
    __syncthreads();

    auto issue = [&](int c) {
        int buf = c % 3;
        uint32_t mb = sb + 8 + (uint32_t)buf * 16;
        uint32_t base = sb + 1024 + (uint32_t)buf * BUFB;
        MBARRIER_EXPECT_TX(mb, BUFB);
        const char* ah = (const char*)Ahi + ((size_t)c * ROWSP + bm) * 128;
        const char* al = (const char*)Alo + ((size_t)c * ROWSP + bm) * 128;
        const char* bh = (const char*)Bhi + ((size_t)c * NB + n0) * 128;
        const char* bl = (const char*)Blo + ((size_t)c * NB + n0) * 128;
        BULK_G2S(base,               ah, 16384, mb);
        BULK_G2S(base + 16384,       al, 16384, mb);
        BULK_G2S(base + 32768,       bh, BNB,   mb);
        BULK_G2S(base + 32768 + BNB, bl, BNB,   mb);
    };
    if (tid == 0) {
#pragma unroll
        for (int c = 0; c < 3 && c < NCHUNK; ++c) issue(c);
    }

    const int arow = lane & 15;
    const int akb = (lane >> 4) << 3;
    const uint32_t aRowOff = (uint32_t)(wm * WR + arow) * 128;
    const uint32_t aSw = (uint32_t)(arow & 7) << 4;
    const int brow = (lane & 7) + ((lane >> 4) << 3);
    const int bkb = ((lane >> 3) & 1) << 3;
    const uint32_t bRowOff = (uint32_t)(wn * WC + brow) * 128;
    const uint32_t bSw = (uint32_t)(brow & 7) << 4;

    float acc[MT][NT][4];
#pragma unroll
    for (int i = 0; i < MT; ++i)
#pragma unroll
        for (int j = 0; j < NT; ++j)
#pragma unroll
            for (int q = 0; q < 4; ++q) acc[i][j][q] = 0.f;

    for (int c = 0; c < NCHUNK; ++c) {
        const int buf = c % 3;
        mbar_wait(sb + 8 + (uint32_t)buf * 16, (uint32_t)(c / 3) & 1);

        const uint32_t base = sb + 1024 + (uint32_t)buf * BUFB;
        const uint32_t aHiS = base, aLoS = base + 16384;
        const uint32_t bHiS = base + 32768, bLoS = base + 32768 + BNB;

#pragma unroll
        for (int ks = 0; ks < 4; ++ks) {
            uint32_t ah[MT][4], al[MT][4], bh[NT][2], bl[NT][2];
            const uint32_t akByte = ((uint32_t)((ks * 16 + akb) * 2)) ^ aSw;
#pragma unroll
            for (int mt = 0; mt < MT; ++mt) {
                uint32_t o = aRowOff + (uint32_t)mt * 2048 + akByte;
                ldsm4(ah[mt], aHiS + o);
                ldsm4(al[mt], aLoS + o);
            }
            const uint32_t bkByte = ((uint32_t)((ks * 16 + bkb) * 2)) ^ bSw;
#pragma unroll
            for (int p = 0; p < NT / 2; ++p) {
                uint32_t o = bRowOff + (uint32_t)p * 2048 + bkByte;
                uint32_t t[4];
                ldsm4(t, bHiS + o);
                bh[2 * p][0] = t[0]; bh[2 * p][1] = t[1];
                bh[2 * p + 1][0] = t[2]; bh[2 * p + 1][1] = t[3];
                ldsm4(t, bLoS + o);
                bl[2 * p][0] = t[0]; bl[2 * p][1] = t[1];
                bl[2 * p + 1][0] = t[2]; bl[2 * p + 1][1] = t[3];
            }
#pragma unroll
            for (int mt = 0; mt < MT; ++mt)
#pragma unroll
                for (int nt = 0; nt < NT; ++nt)
                    mma_bf16(acc[mt][nt], ah[mt], bh[nt]);
#pragma unroll
            for (int mt = 0; mt < MT; ++mt)
#pragma unroll
                for (int nt = 0; nt < NT; ++nt)
                    mma_bf16(acc[mt][nt], ah[mt], bl[nt]);
#pragma unroll
            for (int mt = 0; mt < MT; ++mt)
#pragma unroll
                for (int nt = 0; nt < NT; ++nt)
                    mma_bf16(acc[mt][nt], al[mt], bh[nt]);
        }
        __syncthreads();
        if (tid == 0 && c + 3 < NCHUNK) issue(c + 3);
    }

    // epilogue
    const int r0 = bm + wm * WR + (lane >> 2);
#pragma unroll
    for (int mt = 0; mt < MT; ++mt) {
#pragma unroll
        for (int nt = 0; nt < NT; ++nt) {
            int row = r0 + mt * 16;
            int col = n0 + wn * WC + nt * 8 + (lane & 3) * 2;
            float bv0 = __ldg(bias + col), bv1 = __ldg(bias + col + 1);
            if (SPLIT_OUT) {
                int pl = col >> 6, kk = col & 63;
                size_t pbase = (size_t)pl * ROWSP * 128;
                uint32_t xoff = ((uint32_t)kk * 2);
#pragma unroll
                for (int half = 0; half < 2; ++half) {
                    int r = row + half * 8;
                    if (r >= NN) continue;
                    float v0 = fmaxf(acc[mt][nt][2 * half + 0] + bv0, 0.f);
                    float v1 = fmaxf(acc[mt][nt][2 * half + 1] + bv1, 0.f);
                    __nv_bfloat16 h0 = __float2bfloat16(v0);
                    __nv_bfloat16 h1 = __float2bfloat16(v1);
                    __nv_bfloat162 hv(h0, h1);
                    __nv_bfloat162 lv(__float2bfloat16(v0 - __bfloat162float(h0)),
                                      __float2bfloat16(v1 - __bfloat162float(h1)));
                    uint32_t off = (uint32_t)r * 128 + (xoff ^ (((uint32_t)r & 7) << 4));
                    *(__nv_bfloat162*)((char*)Ohi + pbase + off) = hv;
                    *(__nv_bfloat162*)((char*)Olo + pbase + off) = lv;
                }
            } else {
#pragma unroll
                for (int half = 0; half < 2; ++half) {
                    int r = row + half * 8;
                    if (r >= NN) continue;
                    float2 v;
                    v.x = acc[mt][nt][2 * half + 0] + bv0;
                    v.y = acc[mt][nt][2 * half + 1] + bv1;
                    *(float2*)&C[(size_t)r * NB + col] = v;
                }
            }
        }
    }
    __syncthreads();
    if (tid == 0) { MBARRIER_INVAL(sb + 8); MBARRIER_INVAL(sb + 24); MBARRIER_INVAL(sb + 40); }
}

// ---------------- row_ptr build ---------------------------------------------
__global__ void build_row_ptr(const int* __restrict__ erow) {
    int r = blockIdx.x * blockDim.x + threadIdx.x;
    if (r > NN) return;
    int lo = 0, hi = NE;
    while (lo < hi) {
        int mid = (lo + hi) >> 1;
        if (erow[mid] < r) lo = mid + 1; else hi = mid;
    }
    g_rp[r] = lo;
}

// ---------------- fused CSR SpMM + Chebyshev recurrence ---------------------
// 8 threads/row; each thread owns float4 slots ch and ch+8 (two coalesced
// 128B segments). Halves redundant ecol/evals loads, doubles per-thread MLP.
__global__ void spmm_cheb(const int* __restrict__ ecol, const float* __restrict__ evals,
                          const float* __restrict__ gamma, float* __restrict__ z,
                          int cur, int prev, int nxt, int k, int first, int last) {
    int t = blockIdx.x * blockDim.x + threadIdx.x;
    int row = t >> 3;
    int ch = t & 7;
    if (row >= NN) return;

    const float4* vcur = (const float4*)g_tb[cur];
    int s = g_rp[row];
    int e = g_rp[row + 1];

    float4 accA = make_float4(0.f, 0.f, 0.f, 0.f);
    float4 accB = make_float4(0.f, 0.f, 0.f, 0.f);
    int i = s;
    int nb = (e - s) >> 1;
    for (int b = 0; b < nb; ++b, i += 2) {
        int c0 = __ldg(ecol + i), c1 = __ldg(ecol + i + 1);
        float w0 = __ldg(evals + i), w1 = __ldg(evals + i + 1);
        const float4* p0 = vcur + (size_t)c0 * 16 + ch;
        const float4* p1 = vcur + (size_t)c1 * 16 + ch;
        float4 a0 = __ldg(p0), b0 = __ldg(p0 + 8);
        float4 a1 = __ldg(p1), b1 = __ldg(p1 + 8);
        accA.x = fmaf(w0, a0.x, accA.x); accA.y = fmaf(w0, a0.y, accA.y);
        accA.z = fmaf(w0, a0.z, accA.z); accA.w = fmaf(w0, a0.w, accA.w);
        accB.x = fmaf(w0, b0.x, accB.x); accB.y = fmaf(w0, b0.y, accB.y);
        accB.z = fmaf(w0, b0.z, accB.z); accB.w = fmaf(w0, b0.w, accB.w);
        accA.x = fmaf(w1, a1.x, accA.x); accA.y = fmaf(w1, a1.y, accA.y);
        accA.z = fmaf(w1, a1.z, accA.z); accA.w = fmaf(w1, a1.w, accA.w);
        accB.x = fmaf(w1, b1.x, accB.x); accB.y = fmaf(w1, b1.y, accB.y);
        accB.z = fmaf(w1, b1.z, accB.z); accB.w = fmaf(w1, b1.w, accB.w);
    }
    if (i < e) {
        int c0 = __ldg(ecol + i);
        float w0 = __ldg(evals + i);
        const float4* p0 = vcur + (size_t)c0 * 16 + ch;
        float4 a0 = __ldg(p0), b0 = __ldg(p0 + 8);
        accA.x = fmaf(w0, a0.x, accA.x); accA.y = fmaf(w0, a0.y, accA.y);
        accA.z = fmaf(w0, a0.z, accA.z); accA.w = fmaf(w0, a0.w, accA.w);
        accB.x = fmaf(w0, b0.x, accB.x); accB.y = fmaf(w0, b0.y, accB.y);
        accB.z = fmaf(w0, b0.z, accB.z); accB.w = fmaf(w0, b0.w, accB.w);
    }

    float4* vnext = (float4*)g_tb[nxt];
    float4* z4 = (float4*)z;
    float4 accs[2] = {accA, accB};

    if (first) {
        float g0 = gamma[0], g1 = gamma[1];
#pragma unroll
        for (int half = 0; half < 2; ++half) {
            size_t o = (size_t)row * 16 + ch + half * 8;
            float4 acc = accs[half];
            float4 h = vcur[o];
            vnext[o] = acc;
            float4 zz;
            zz.x = g0 * h.x + g1 * acc.x;
            zz.y = g0 * h.y + g1 * acc.y;
            zz.z = g0 * h.z + g1 * acc.z;
            zz.w = g0 * h.w + g1 * acc.w;
            z4[o] = zz;
        }
    } else {
        const float4* vprev = (const float4*)g_tb[prev];
        float g = gamma[k];
#pragma unroll
        for (int half = 0; half < 2; ++half) {
            size_t o = (size_t)row * 16 + ch + half * 8;
            float4 acc = accs[half];
            float4 p = vprev[o];
            float4 tn;
            tn.x = 2.f * acc.x - p.x;
            tn.y = 2.f * acc.y - p.y;
            tn.z = 2.f * acc.z - p.z;
            tn.w = 2.f * acc.w - p.w;
            if (!last) vnext[o] = tn;
            float4 zz = z4[o];
            zz.x = fmaf(g, tn.x, zz.x);
            zz.y = fmaf(g, tn.y, zz.y);
            zz.z = fmaf(g, tn.z, zz.z);
            zz.w = fmaf(g, tn.w, zz.w);
            z4[o] = zz;
        }
    }
}

// ---------------- launch ----------------------------------------------------
extern "C" void kernel_launch(void* const* d_in, const int* in_sizes, int n_in,
                              void* d_out, int out_size) {
    const float* x     = (const float*)d_in[0];
    const int*   erow  = (const int*)d_in[1];
    const int*   ecol  = (const int*)d_in[2];
    const float* evals = (const float*)d_in[3];
    const float* W1    = (const float*)d_in[4];
    const float* b1    = (const float*)d_in[5];
    const float* W2    = (const float*)d_in[6];
    const float* b2    = (const float*)d_in[7];
    const float* gamma = (const float*)d_in[8];
    float* z = (float*)d_out;

    float *tb0;
    __nv_bfloat16 *ahi, *alo, *hhi, *hlo, *w1hi, *w1lo, *w2hi, *w2lo;
    cudaGetSymbolAddress((void**)&tb0, g_tb);
    cudaGetSymbolAddress((void**)&ahi, g_ahi);
    cudaGetSymbolAddress((void**)&alo, g_alo);
    cudaGetSymbolAddress((void**)&hhi, g_hhi);
    cudaGetSymbolAddress((void**)&hlo, g_hlo);
    cudaGetSymbolAddress((void**)&w1hi, g_w1hi);
    cudaGetSymbolAddress((void**)&w1lo, g_w1lo);
    cudaGetSymbolAddress((void**)&w2hi, g_w2hi);
    cudaGetSymbolAddress((void**)&w2lo, g_w2lo);

    // dynamic smem: 1024 + 3 * (32768 + 2*BN*128)
    constexpr int SMEM1 = 1024 + 3 * (32768 + 2 * 128 * 128);  // 197632
    constexpr int SMEM2 = 1024 + 3 * (32768 + 2 * 64 * 128);   // 148480
    cudaFuncSetAttribute(tc_gemm<128, 8, 2, 4, true>,
                         cudaFuncAttributeMaxDynamicSharedMemorySize, SMEM1);
    cudaFuncSetAttribute(tc_gemm<64, 4, 4, 2, false>,
                         cudaFuncAttributeMaxDynamicSharedMemorySize, SMEM2);

    const int MTILES = (NN + 127) / 128;  // 782

    prep_w<8><<<(IND * HID + 255) / 256, 256>>>(W1, IND, w1hi, w1lo);
    prep_w<6><<<(HID * NC + 255) / 256, 256>>>(W2, HID, w2hi, w2lo);

    {
        long long tot = (long long)NN * (IND / 8);
        prep_a<9><<<(unsigned)((tot + 255) / 256), 256>>>(x, ahi, alo);
    }
    // GEMM1: relu(x@W1 + b1) -> split bf16 planes (g_hhi/g_hlo)  [R6 config]
    {
        dim3 grid(2, MTILES);
        tc_gemm<128, 8, 2, 4, true><<<grid, 256, SMEM1>>>(
            ahi, alo, w1hi, w1lo, b1, nullptr, hhi, hlo, HID);
    }
    // GEMM2: h@W2 + b2 -> g_tb[0] fp32  [R6 config]
    {
        dim3 grid(1, MTILES);
        tc_gemm<64, 4, 4, 2, false><<<grid, 256, SMEM2>>>(
            hhi, hlo, w2hi, w2lo, b2, tb0, nullptr, nullptr, NC);
    }

    build_row_ptr<<<(NN + 256) / 256, 256>>>(erow);

    const int SPMM_BLOCKS = (NN * 8 + 255) / 256;
    spmm_cheb<<<SPMM_BLOCKS, 256>>>(ecol, evals, gamma, z, 0, 0, 1, 1, 1, 0);
    int p = 0, c = 1;
    for (int k = 2; k <= 8; ++k) {
        int n = 3 - p - c;
        spmm_cheb<<<SPMM_BLOCKS, 256>>>(ecol, evals, gamma, z, c, p, n, k, 0, k == 8);
        p = c; c = n;
    }
}